// round 14
// baseline (speedup 1.0000x reference)
#include <cuda_runtime.h>
#include <cuda_fp16.h>
#include <math.h>
#include <stdint.h>

#define N_NODES 200000
#define N_PAD   200064
#define N_EDGES 3200000
#define G_GRAPHS 8192
#define HID 256
#define H2 128
#define CCOLS 512
#define EPS 1e-5f
#define SCAN_CHUNK 2048
#define NCH 4

// ---------------- scratch (device globals; no runtime alloc) ----------------
__device__ __half g_hX[2 * (size_t)N_PAD * 128];
__device__ __half g_hA[(size_t)N_PAD * HID];
__device__ __half g_hB[(size_t)N_PAD * HID];
__device__ __half g_hC[(size_t)N_PAD * HID];
__device__ __half g_hD[(size_t)N_PAD * 128];
__device__ __half g_hA1[(size_t)N_PAD * 128];     // tower-1 L1 agg output
__device__ __half g_w1h[128 * 256];
__device__ __half g_w2h[256 * 256];
__device__ __half g_w3h[256 * 256];
__device__ __half g_w4h[256 * 128];
__device__ float g_dinv[2 * N_NODES];
__device__ int   g_deg[2 * N_NODES];
__device__ int   g_off[2 * N_NODES];
__device__ int   g_cur[2 * N_NODES];
__device__ int   g_bsum[2 * 128];
__device__ int2  g_edge[2 * (size_t)N_EDGES];
__device__ float g_cnt[2 * G_GRAPHS];
__device__ float g_c[(size_t)G_GRAPHS * CCOLS];
__device__ float g_t1[2 * (size_t)G_GRAPHS * HID];
__device__ float g_t2[(size_t)G_GRAPHS * H2];
__device__ float g_mu[HID];
__device__ float g_istd[HID];

__device__ __forceinline__ void red_add_v4(float* addr, float4 v) {
    asm volatile("red.global.add.v4.f32 [%0], {%1, %2, %3, %4};"
                 :: "l"(addr), "f"(v.x), "f"(v.y), "f"(v.z), "f"(v.w)
                 : "memory");
}

// ---------------- utility kernels ----------------
__global__ void fill_kernel(float* __restrict__ p, float v, size_t n) {
    size_t i = (size_t)blockIdx.x * blockDim.x + threadIdx.x;
    if (i < n) p[i] = v;
}

__global__ void fillh_kernel(__half* __restrict__ p, size_t n2) {
    size_t i = (size_t)blockIdx.x * blockDim.x + threadIdx.x;
    if (i < n2) ((__half2*)p)[i] = __floats2half2_rn(0.f, 0.f);
}

__global__ void f2h_kernel(const float* __restrict__ in, __half* __restrict__ out, size_t n2) {
    size_t i = (size_t)blockIdx.x * blockDim.x + threadIdx.x;
    if (i < n2) {
        float2 v = ((const float2*)in)[i];
        ((__half2*)out)[i] = __floats2half2_rn(v.x, v.y);
    }
}

__global__ void zero_int_kernel(int* __restrict__ p, int n) {
    int i = blockIdx.x * blockDim.x + threadIdx.x;
    if (i < n) p[i] = 0;
}

__global__ void hist_kernel(const int* __restrict__ cols, int* __restrict__ deg, int nE) {
    int i = blockIdx.x * blockDim.x + threadIdx.x;
    if (i < nE) atomicAdd(&deg[cols[i]], 1);
}

__global__ void dinv_kernel(const int* __restrict__ deg, float* __restrict__ dinv, int n) {
    int i = blockIdx.x * blockDim.x + threadIdx.x;
    if (i < n) dinv[i] = rsqrtf((float)deg[i] + 1.0f);
}

// ---------------- exclusive scan ----------------
__global__ void scan_partial_kernel(const int* __restrict__ deg, int* __restrict__ bsum, int n) {
    __shared__ int sh[256];
    int t = threadIdx.x;
    int base = blockIdx.x * SCAN_CHUNK + t * 8;
    int s = 0;
#pragma unroll
    for (int k = 0; k < 8; k++)
        if (base + k < n) s += deg[base + k];
    sh[t] = s;
    __syncthreads();
    for (int o = 128; o > 0; o >>= 1) {
        if (t < o) sh[t] += sh[t + o];
        __syncthreads();
    }
    if (t == 0) bsum[blockIdx.x] = sh[0];
}

__global__ void scan_top_kernel(int* __restrict__ bsum, int nb) {
    __shared__ int sh[256];
    int t = threadIdx.x;
    int v = (t < nb) ? bsum[t] : 0;
    sh[t] = v;
    __syncthreads();
    for (int o = 1; o < 256; o <<= 1) {
        int x = (t >= o) ? sh[t - o] : 0;
        __syncthreads();
        sh[t] += x;
        __syncthreads();
    }
    if (t < nb) bsum[t] = sh[t] - v;
}

__global__ void scan_apply_kernel(const int* __restrict__ deg, const int* __restrict__ bsum,
                                  int* __restrict__ off, int* __restrict__ cur, int n) {
    __shared__ int sh[256];
    int t = threadIdx.x;
    int base = blockIdx.x * SCAN_CHUNK + t * 8;
    int loc[8];
    int s = 0;
#pragma unroll
    for (int k = 0; k < 8; k++) {
        loc[k] = (base + k < n) ? deg[base + k] : 0;
        s += loc[k];
    }
    sh[t] = s;
    __syncthreads();
    for (int o = 1; o < 256; o <<= 1) {
        int x = (t >= o) ? sh[t - o] : 0;
        __syncthreads();
        sh[t] += x;
        __syncthreads();
    }
    int run = bsum[blockIdx.x] + sh[t] - s;
#pragma unroll
    for (int k = 0; k < 8; k++) {
        if (base + k < n) {
            off[base + k] = run;
            cur[base + k] = run;
            run += loc[k];
        }
    }
}

__global__ void csr_fill_kernel(const int* __restrict__ rows, const int* __restrict__ cols,
                                const float* __restrict__ dinv, int* __restrict__ cur,
                                int2* __restrict__ edges, int nE) {
    int e = blockIdx.x * blockDim.x + threadIdx.x;
    if (e >= nE) return;
    int c = cols[e], r = rows[e];
    int p = atomicAdd(&cur[c], 1);
    __half2 w2 = __float2half2_rn(dinv[r]);
    edges[p] = make_int2(r, *reinterpret_cast<int*>(&w2));
}

// ---------------- CSR gather aggregation (fp16 HFMA2), node range [n0, n1) ----
template <int D, bool POOL>
__global__ __launch_bounds__(256) void agg_csr_h(
    const __half* __restrict__ in, __half* __restrict__ out,
    const int* __restrict__ off, const int2* __restrict__ edges,
    const float* __restrict__ dinv,
    const int* __restrict__ batch, const float* __restrict__ bias,
    float* __restrict__ cbuf, int coff, int n0, int n1) {
    int node = n0 + blockIdx.x * (blockDim.x >> 5) + (threadIdx.x >> 5);
    if (node >= n1) return;
    int lane = threadIdx.x & 31;
    int s = off[node];
    int e = (node == N_NODES - 1) ? N_EDGES : off[node + 1];
    float dc = dinv[node];

    constexpr int V2 = D / 64;
    __half2 acc0[V2], acc1[V2];
#pragma unroll
    for (int v = 0; v < V2; v++) {
        acc0[v] = __floats2half2_rn(0.f, 0.f);
        acc1[v] = __floats2half2_rn(0.f, 0.f);
    }

    if (D == 256) {
        int j = s;
        for (; j + 1 < e; j += 2) {
            int2 e0 = edges[j], e1 = edges[j + 1];
            __half2 w0 = *reinterpret_cast<__half2*>(&e0.y);
            __half2 w1 = *reinterpret_cast<__half2*>(&e1.y);
            uint4 x0 = *((const uint4*)(in + (size_t)e0.x * D) + lane);
            uint4 x1 = *((const uint4*)(in + (size_t)e1.x * D) + lane);
            const __half2* p0 = (const __half2*)&x0;
            const __half2* p1 = (const __half2*)&x1;
#pragma unroll
            for (int v = 0; v < 4; v++) {
                acc0[v] = __hfma2(p0[v], w0, acc0[v]);
                acc1[v] = __hfma2(p1[v], w1, acc1[v]);
            }
        }
        if (j < e) {
            int2 e0 = edges[j];
            __half2 w0 = *reinterpret_cast<__half2*>(&e0.y);
            uint4 x0 = *((const uint4*)(in + (size_t)e0.x * D) + lane);
            const __half2* p0 = (const __half2*)&x0;
#pragma unroll
            for (int v = 0; v < 4; v++) acc0[v] = __hfma2(p0[v], w0, acc0[v]);
        }
    } else {
        int j = s;
        for (; j + 1 < e; j += 2) {
            int2 e0 = edges[j], e1 = edges[j + 1];
            __half2 w0 = *reinterpret_cast<__half2*>(&e0.y);
            __half2 w1 = *reinterpret_cast<__half2*>(&e1.y);
            uint2 x0 = *((const uint2*)(in + (size_t)e0.x * D) + lane);
            uint2 x1 = *((const uint2*)(in + (size_t)e1.x * D) + lane);
            const __half2* p0 = (const __half2*)&x0;
            const __half2* p1 = (const __half2*)&x1;
#pragma unroll
            for (int v = 0; v < 2; v++) {
                acc0[v] = __hfma2(p0[v], w0, acc0[v]);
                acc1[v] = __hfma2(p1[v], w1, acc1[v]);
            }
        }
        if (j < e) {
            int2 e0 = edges[j];
            __half2 w0 = *reinterpret_cast<__half2*>(&e0.y);
            uint2 x0 = *((const uint2*)(in + (size_t)e0.x * D) + lane);
            const __half2* p0 = (const __half2*)&x0;
#pragma unroll
            for (int v = 0; v < 2; v++) acc0[v] = __hfma2(p0[v], w0, acc0[v]);
        }
    }

    float accf[2 * V2];
    if (D == 256) {
        uint4 u = *((const uint4*)(in + (size_t)node * D) + lane);
        const __half2* hp = (const __half2*)&u;
#pragma unroll
        for (int v = 0; v < 4; v++) {
            float2 f0 = __half22float2(acc0[v]);
            float2 f1 = __half22float2(acc1[v]);
            float2 fs = __half22float2(hp[v]);
            accf[2 * v]     = (f0.x + f1.x + dc * fs.x) * dc;
            accf[2 * v + 1] = (f0.y + f1.y + dc * fs.y) * dc;
        }
    } else {
        uint2 u = *((const uint2*)(in + (size_t)node * D) + lane);
        const __half2* hp = (const __half2*)&u;
#pragma unroll
        for (int v = 0; v < 2; v++) {
            float2 f0 = __half22float2(acc0[v]);
            float2 f1 = __half22float2(acc1[v]);
            float2 fs = __half22float2(hp[v]);
            accf[2 * v]     = (f0.x + f1.x + dc * fs.x) * dc;
            accf[2 * v + 1] = (f0.y + f1.y + dc * fs.y) * dc;
        }
    }

    if (POOL) {
        float4 b = *(const float4*)&bias[lane * 4];
        float4 v0;
        v0.x = fmaxf(accf[0] + b.x, 0.0f);
        v0.y = fmaxf(accf[1] + b.y, 0.0f);
        v0.z = fmaxf(accf[2] + b.z, 0.0f);
        v0.w = fmaxf(accf[3] + b.w, 0.0f);
        red_add_v4(&cbuf[(size_t)batch[node] * CCOLS + coff + lane * 4], v0);
    } else if (D == 256) {
        uint4 o;
        __half2* op = (__half2*)&o;
#pragma unroll
        for (int v = 0; v < 4; v++) op[v] = __floats2half2_rn(accf[2 * v], accf[2 * v + 1]);
        *((uint4*)(out + (size_t)node * D) + lane) = o;
    } else {
        uint2 o;
        __half2* op = (__half2*)&o;
#pragma unroll
        for (int v = 0; v < 2; v++) op[v] = __floats2half2_rn(accf[2 * v], accf[2 * v + 1]);
        *((uint2*)(out + (size_t)node * D) + lane) = o;
    }
}

__global__ void count_kernel(const int* __restrict__ batch, float* __restrict__ cnt, int n) {
    int i = blockIdx.x * blockDim.x + threadIdx.x;
    if (i < n) atomicAdd(&cnt[batch[i]], 1.0f);
}

__global__ void pool_div_kernel(float* __restrict__ c, const float* __restrict__ cnt, int coff) {
    int idx = blockIdx.x * blockDim.x + threadIdx.x;
    if (idx >= G_GRAPHS * H2) return;
    int g = idx >> 7, d = idx & 127;
    c[(size_t)g * CCOLS + coff + d] *= 1.0f / fmaxf(cnt[g], 1.0f);
}

// ---------------- fp16 HMMA GEMM, cp.async double-buffered ----------------
#define APAD 40
template <bool RELU, bool BIAS>
__global__ __launch_bounds__(256) void hgemm(
    const __half* __restrict__ A, const __half* __restrict__ W,
    const float* __restrict__ bias, __half* __restrict__ C,
    int M, int K, int N, int ldc) {
    __shared__ __half As[2][128][APAD];
    __shared__ __half Bst[2][64][APAD];

    int tid = threadIdx.x;
    int bm = blockIdx.y * 128, bn = blockIdx.x * 64;
    int warp = tid >> 5, lane = tid & 31;
    int wm = (warp & 3) * 32, wn = (warp >> 2) * 32;
    int g = lane >> 2, tig = lane & 3;

    int arow0 = (tid + 0) >> 2,   ac8_0 = ((tid + 0) & 3) << 3;
    int arow1 = (tid + 256) >> 2, ac8_1 = ((tid + 256) & 3) << 3;
    int bk = tid >> 3, bn0 = (tid & 7) << 3;

    float acc[2][4][4] = {};

    {
        uint32_t d0 = (uint32_t)__cvta_generic_to_shared(&As[0][arow0][ac8_0]);
        uint32_t d1 = (uint32_t)__cvta_generic_to_shared(&As[0][arow1][ac8_1]);
        const __half* s0 = A + (size_t)(bm + arow0) * K + ac8_0;
        const __half* s1 = A + (size_t)(bm + arow1) * K + ac8_1;
        asm volatile("cp.async.ca.shared.global [%0], [%1], 16;" :: "r"(d0), "l"(s0));
        asm volatile("cp.async.ca.shared.global [%0], [%1], 16;" :: "r"(d1), "l"(s1));
        asm volatile("cp.async.commit_group;");
        uint4 bv = *(const uint4*)(W + (size_t)bk * N + bn + bn0);
        const __half* hv = (const __half*)&bv;
        asm volatile("cp.async.wait_group 0;" ::: "memory");
#pragma unroll
        for (int i = 0; i < 8; i++) Bst[0][bn0 + i][bk] = hv[i];
        __syncthreads();
    }

    int nIter = K >> 5;
    for (int it = 0; it < nIter; it++) {
        int s = it & 1;
        if (it + 1 < nIter) {
            int k0 = (it + 1) << 5;
            uint32_t d0 = (uint32_t)__cvta_generic_to_shared(&As[s ^ 1][arow0][ac8_0]);
            uint32_t d1 = (uint32_t)__cvta_generic_to_shared(&As[s ^ 1][arow1][ac8_1]);
            const __half* s0 = A + (size_t)(bm + arow0) * K + k0 + ac8_0;
            const __half* s1 = A + (size_t)(bm + arow1) * K + k0 + ac8_1;
            asm volatile("cp.async.ca.shared.global [%0], [%1], 16;" :: "r"(d0), "l"(s0));
            asm volatile("cp.async.ca.shared.global [%0], [%1], 16;" :: "r"(d1), "l"(s1));
            asm volatile("cp.async.commit_group;");
            uint4 bv = *(const uint4*)(W + (size_t)(k0 + bk) * N + bn + bn0);
            const __half* hv = (const __half*)&bv;
#pragma unroll
            for (int i = 0; i < 8; i++) Bst[s ^ 1][bn0 + i][bk] = hv[i];
        }

#pragma unroll
        for (int k16 = 0; k16 < 32; k16 += 16) {
            uint32_t a[2][4], b[4][2];
#pragma unroll
            for (int mt = 0; mt < 2; mt++) {
                int m = wm + mt * 16 + g;
                a[mt][0] = *(const uint32_t*)&As[s][m][k16 + 2 * tig];
                a[mt][1] = *(const uint32_t*)&As[s][m + 8][k16 + 2 * tig];
                a[mt][2] = *(const uint32_t*)&As[s][m][k16 + 2 * tig + 8];
                a[mt][3] = *(const uint32_t*)&As[s][m + 8][k16 + 2 * tig + 8];
            }
#pragma unroll
            for (int nt = 0; nt < 4; nt++) {
                int n = wn + nt * 8 + g;
                b[nt][0] = *(const uint32_t*)&Bst[s][n][k16 + 2 * tig];
                b[nt][1] = *(const uint32_t*)&Bst[s][n][k16 + 2 * tig + 8];
            }
#pragma unroll
            for (int mt = 0; mt < 2; mt++)
#pragma unroll
                for (int nt = 0; nt < 4; nt++) {
                    asm volatile(
                        "mma.sync.aligned.m16n8k16.row.col.f32.f16.f16.f32 "
                        "{%0,%1,%2,%3}, {%4,%5,%6,%7}, {%8,%9}, {%0,%1,%2,%3};"
                        : "+f"(acc[mt][nt][0]), "+f"(acc[mt][nt][1]),
                          "+f"(acc[mt][nt][2]), "+f"(acc[mt][nt][3])
                        : "r"(a[mt][0]), "r"(a[mt][1]), "r"(a[mt][2]), "r"(a[mt][3]),
                          "r"(b[nt][0]), "r"(b[nt][1]));
                }
        }

        if (it + 1 < nIter)
            asm volatile("cp.async.wait_group 0;" ::: "memory");
        __syncthreads();
    }

#pragma unroll
    for (int mt = 0; mt < 2; mt++) {
        int row0 = bm + wm + mt * 16 + g;
#pragma unroll
        for (int nt = 0; nt < 4; nt++) {
            int col = bn + wn + nt * 8 + 2 * tig;
            float b0 = 0.f, b1 = 0.f;
            if (BIAS) { b0 = bias[col]; b1 = bias[col + 1]; }
            float v0 = acc[mt][nt][0] + b0;
            float v1 = acc[mt][nt][1] + b1;
            float v2 = acc[mt][nt][2] + b0;
            float v3 = acc[mt][nt][3] + b1;
            if (RELU) {
                v0 = fmaxf(v0, 0.f); v1 = fmaxf(v1, 0.f);
                v2 = fmaxf(v2, 0.f); v3 = fmaxf(v3, 0.f);
            }
            *(__half2*)&C[(size_t)row0 * ldc + col] = __floats2half2_rn(v0, v1);
            *(__half2*)&C[(size_t)(row0 + 8) * ldc + col] = __floats2half2_rn(v2, v3);
        }
    }
}

// ---------------- tf32 GEMM (notes/head) ----------------
__device__ __forceinline__ void tf32_split(float x, uint32_t& h, uint32_t& l) {
    asm("cvt.rna.tf32.f32 %0, %1;" : "=r"(h) : "f"(x));
    float r = x - __uint_as_float(h);
    asm("cvt.rna.tf32.f32 %0, %1;" : "=r"(l) : "f"(r));
}

__device__ __forceinline__ void mma_tf32(float* c,
                                         uint32_t a0, uint32_t a1, uint32_t a2, uint32_t a3,
                                         uint32_t b0, uint32_t b1) {
    asm volatile(
        "mma.sync.aligned.m16n8k8.row.col.f32.tf32.tf32.f32 "
        "{%0,%1,%2,%3}, {%4,%5,%6,%7}, {%8,%9}, {%0,%1,%2,%3};"
        : "+f"(c[0]), "+f"(c[1]), "+f"(c[2]), "+f"(c[3])
        : "r"(a0), "r"(a1), "r"(a2), "r"(a3), "r"(b0), "r"(b1));
}

template <bool RELU, bool BIAS>
__global__ __launch_bounds__(256) void tc_gemm(
    const float* __restrict__ A, const float* __restrict__ W,
    const float* __restrict__ bias, float* __restrict__ C,
    int M, int K, int N, int ldc, int coff) {
    __shared__ float As[128][20];
    __shared__ float Bs[16][72];

    int tid = threadIdx.x;
    int bm = blockIdx.y * 128, bn = blockIdx.x * 64;
    int warp = tid >> 5, lane = tid & 31;
    int wm = (warp & 3) * 32, wn = (warp >> 2) * 32;
    int g = lane >> 2, tig = lane & 3;

    float acc[2][4][4] = {};

    for (int k0 = 0; k0 < K; k0 += 16) {
#pragma unroll
        for (int i = 0; i < 2; i++) {
            int idx = tid + i * 256;
            int row = idx >> 2, c4 = (idx & 3) << 2;
            float4 v = *(const float4*)&A[(size_t)(bm + row) * K + k0 + c4];
            As[row][c4 + 0] = v.x; As[row][c4 + 1] = v.y;
            As[row][c4 + 2] = v.z; As[row][c4 + 3] = v.w;
        }
        {
            int row = tid >> 4, c4 = (tid & 15) << 2;
            float4 v = *(const float4*)&W[(size_t)(k0 + row) * N + bn + c4];
            Bs[row][c4 + 0] = v.x; Bs[row][c4 + 1] = v.y;
            Bs[row][c4 + 2] = v.z; Bs[row][c4 + 3] = v.w;
        }
        __syncthreads();

#pragma unroll
        for (int k8 = 0; k8 < 16; k8 += 8) {
            uint32_t ah[2][4], al[2][4], bh[4][2], bl[4][2];
#pragma unroll
            for (int mt = 0; mt < 2; mt++) {
                int m = wm + mt * 16 + g;
                tf32_split(As[m][k8 + tig],         ah[mt][0], al[mt][0]);
                tf32_split(As[m + 8][k8 + tig],     ah[mt][1], al[mt][1]);
                tf32_split(As[m][k8 + tig + 4],     ah[mt][2], al[mt][2]);
                tf32_split(As[m + 8][k8 + tig + 4], ah[mt][3], al[mt][3]);
            }
#pragma unroll
            for (int nt = 0; nt < 4; nt++) {
                int n = wn + nt * 8 + g;
                tf32_split(Bs[k8 + tig][n],     bh[nt][0], bl[nt][0]);
                tf32_split(Bs[k8 + tig + 4][n], bh[nt][1], bl[nt][1]);
            }
#pragma unroll
            for (int mt = 0; mt < 2; mt++)
#pragma unroll
                for (int nt = 0; nt < 4; nt++) {
                    mma_tf32(acc[mt][nt], ah[mt][0], ah[mt][1], ah[mt][2], ah[mt][3],
                             bh[nt][0], bh[nt][1]);
                    mma_tf32(acc[mt][nt], ah[mt][0], ah[mt][1], ah[mt][2], ah[mt][3],
                             bl[nt][0], bl[nt][1]);
                    mma_tf32(acc[mt][nt], al[mt][0], al[mt][1], al[mt][2], al[mt][3],
                             bh[nt][0], bh[nt][1]);
                }
        }
        __syncthreads();
    }

#pragma unroll
    for (int mt = 0; mt < 2; mt++) {
        int row0 = bm + wm + mt * 16 + g;
#pragma unroll
        for (int nt = 0; nt < 4; nt++) {
            int col = bn + wn + nt * 8 + 2 * tig;
            float b0 = 0.f, b1 = 0.f;
            if (BIAS) { b0 = bias[col]; b1 = bias[col + 1]; }
            float v0 = acc[mt][nt][0] + b0;
            float v1 = acc[mt][nt][1] + b1;
            float v2 = acc[mt][nt][2] + b0;
            float v3 = acc[mt][nt][3] + b1;
            if (RELU) {
                v0 = fmaxf(v0, 0.f); v1 = fmaxf(v1, 0.f);
                v2 = fmaxf(v2, 0.f); v3 = fmaxf(v3, 0.f);
            }
            *(float2*)&C[(size_t)row0 * ldc + coff + col] = make_float2(v0, v1);
            *(float2*)&C[(size_t)(row0 + 8) * ldc + coff + col] = make_float2(v2, v3);
        }
    }
}

// ---------------- batch norm ----------------
__global__ void bn_stats_kernel(const float* __restrict__ X, int C,
                                float* __restrict__ mu, float* __restrict__ istd) {
    int c = blockIdx.x;
    int tid = threadIdx.x;
    float s = 0.f, s2 = 0.f;
    for (int r = tid; r < G_GRAPHS; r += 256) {
        float v = X[(size_t)r * C + c];
        s += v;
        s2 += v * v;
    }
    __shared__ float sh[256], sh2[256];
    sh[tid] = s;
    sh2[tid] = s2;
    __syncthreads();
    for (int o = 128; o > 0; o >>= 1) {
        if (tid < o) {
            sh[tid] += sh[tid + o];
            sh2[tid] += sh2[tid + o];
        }
        __syncthreads();
    }
    if (tid == 0) {
        float m = sh[0] / (float)G_GRAPHS;
        float var = sh2[0] / (float)G_GRAPHS - m * m;
        mu[c] = m;
        istd[c] = rsqrtf(var + EPS);
    }
}

__global__ void bn_apply_kernel(float* __restrict__ X, const float* __restrict__ mu,
                                const float* __restrict__ istd, const float* __restrict__ gamma,
                                const float* __restrict__ beta, int C, int total) {
    int idx = blockIdx.x * blockDim.x + threadIdx.x;
    if (idx >= total) return;
    int c = idx % C;
    X[idx] = (X[idx] - mu[c]) * istd[c] * gamma[c] + beta[c];
}

// ---------------- host launcher ----------------
static inline int ceil_div(long long a, int b) { return (int)((a + b - 1) / b); }

static void build_csr(cudaStream_t st, const int* ei,
                      int* deg, float* dinv, int* bsum, int* off, int* cur, int2* edges) {
    const int TB = 256;
    const int N = N_NODES, E = N_EDGES;
    const int NB_SCAN = ceil_div(N, SCAN_CHUNK);
    const int* rows = ei;
    const int* cols = ei + E;
    zero_int_kernel<<<ceil_div(N, TB), TB, 0, st>>>(deg, N);
    hist_kernel<<<ceil_div(E, TB), TB, 0, st>>>(cols, deg, E);
    dinv_kernel<<<ceil_div(N, TB), TB, 0, st>>>(deg, dinv, N);
    scan_partial_kernel<<<NB_SCAN, 256, 0, st>>>(deg, bsum, N);
    scan_top_kernel<<<1, 256, 0, st>>>(bsum, NB_SCAN);
    scan_apply_kernel<<<NB_SCAN, 256, 0, st>>>(deg, bsum, off, cur, N);
    csr_fill_kernel<<<ceil_div(E, TB), TB, 0, st>>>(rows, cols, dinv, cur, edges, E);
}

extern "C" void kernel_launch(void* const* d_in, const int* in_sizes, int n_in,
                              void* d_out, int out_size) {
    const float* x[2] = {(const float*)d_in[0], (const float*)d_in[1]};
    const int* ei[2] = {(const int*)d_in[2], (const int*)d_in[3]};
    const int* batch[2] = {(const int*)d_in[4], (const int*)d_in[5]};
    const float* notes[2] = {(const float*)d_in[6], (const float*)d_in[7]};
    const float* Wc1 = (const float*)d_in[8];  const float* bc1 = (const float*)d_in[9];
    const float* Wc2 = (const float*)d_in[10]; const float* bc2 = (const float*)d_in[11];
    const float* Wc3 = (const float*)d_in[12]; const float* bc3 = (const float*)d_in[13];
    const float* Wc4 = (const float*)d_in[14]; const float* bc4 = (const float*)d_in[15];
    const float* Wn1 = (const float*)d_in[16]; const float* bn1b = (const float*)d_in[17];
    const float* Wn2 = (const float*)d_in[18]; const float* bn2b = (const float*)d_in[19];
    const float* Wf1 = (const float*)d_in[20]; const float* bf1 = (const float*)d_in[21];
    const float* g1 = (const float*)d_in[22];  const float* be1 = (const float*)d_in[23];
    const float* Wf2 = (const float*)d_in[24]; const float* bf2 = (const float*)d_in[25];
    const float* g2 = (const float*)d_in[26];  const float* be2 = (const float*)d_in[27];
    const float* Wf3 = (const float*)d_in[28]; const float* bf3 = (const float*)d_in[29];

    __half *hX, *hA, *hB, *hC, *hD, *hA1, *w1h, *w2h, *w3h, *w4h;
    float *dinv, *cnt, *cbuf, *t1, *t2, *mu, *istd;
    int *deg, *off, *cur, *bsum;
    int2* edges;
    cudaGetSymbolAddress((void**)&hX, g_hX);
    cudaGetSymbolAddress((void**)&hA, g_hA);
    cudaGetSymbolAddress((void**)&hB, g_hB);
    cudaGetSymbolAddress((void**)&hC, g_hC);
    cudaGetSymbolAddress((void**)&hD, g_hD);
    cudaGetSymbolAddress((void**)&hA1, g_hA1);
    cudaGetSymbolAddress((void**)&w1h, g_w1h);
    cudaGetSymbolAddress((void**)&w2h, g_w2h);
    cudaGetSymbolAddress((void**)&w3h, g_w3h);
    cudaGetSymbolAddress((void**)&w4h, g_w4h);
    cudaGetSymbolAddress((void**)&dinv, g_dinv);
    cudaGetSymbolAddress((void**)&deg, g_deg);
    cudaGetSymbolAddress((void**)&off, g_off);
    cudaGetSymbolAddress((void**)&cur, g_cur);
    cudaGetSymbolAddress((void**)&bsum, g_bsum);
    cudaGetSymbolAddress((void**)&edges, g_edge);
    cudaGetSymbolAddress((void**)&cnt, g_cnt);
    cudaGetSymbolAddress((void**)&cbuf, g_c);
    cudaGetSymbolAddress((void**)&t1, g_t1);
    cudaGetSymbolAddress((void**)&t2, g_t2);
    cudaGetSymbolAddress((void**)&mu, g_mu);
    cudaGetSymbolAddress((void**)&istd, g_istd);

    static cudaStream_t sB = 0, sC = 0;
    static cudaEvent_t g_ev[96];
    if (sB == 0) {
        cudaStreamCreateWithFlags(&sB, cudaStreamNonBlocking);
        cudaStreamCreateWithFlags(&sC, cudaStreamNonBlocking);
        for (int i = 0; i < 96; i++)
            cudaEventCreateWithFlags(&g_ev[i], cudaEventDisableTiming);
    }
    int evc = 0;
    cudaStream_t sA = 0;

    const int TB = 256;
    const int G = G_GRAPHS;
    const int N = N_NODES;
    const int PADR = N_PAD - N_NODES;
    const int AGG_FULL = ceil_div(N, 8);
    static const int CST[NCH]  = {0, 50048, 100096, 150144};
    static const int CROW[NCH] = {50048, 50048, 50048, 49920};

    // chunked layer: agg(IN -> MID, Din) on sA per chunk; gemm(MID -> OUT) on sB per chunk
    auto layer = [&](const __half* IN, __half* MID, __half* OUT,
                     const __half* Wh, const float* bias, bool relu,
                     int Din, int Dout,
                     const int* off_, const int2* ed_, const float* dv_) {
        for (int c = 0; c < NCH; c++) {
            int r0 = CST[c], rows = CROW[c];
            int n1 = r0 + rows; if (n1 > N) n1 = N;
            int nblk = ceil_div(n1 - r0, 8);
            if (Din == 128)
                agg_csr_h<128, false><<<nblk, 256, 0, sA>>>(IN, MID, off_, ed_, dv_,
                    (const int*)0, (const float*)0, (float*)0, 0, r0, n1);
            else
                agg_csr_h<256, false><<<nblk, 256, 0, sA>>>(IN, MID, off_, ed_, dv_,
                    (const int*)0, (const float*)0, (float*)0, 0, r0, n1);
            cudaEvent_t e = g_ev[evc++];
            cudaEventRecord(e, sA);
            cudaStreamWaitEvent(sB, e, 0);
            if (relu)
                hgemm<true, true><<<dim3(Dout / 64, rows / 128), 256, 0, sB>>>(
                    MID + (size_t)r0 * Din, Wh, bias, OUT + (size_t)r0 * Dout, rows, Din, Dout, Dout);
            else
                hgemm<false, false><<<dim3(Dout / 64, rows / 128), 256, 0, sB>>>(
                    MID + (size_t)r0 * Din, Wh, bias, OUT + (size_t)r0 * Dout, rows, Din, Dout, Dout);
        }
        cudaEvent_t e = g_ev[evc++];
        cudaEventRecord(e, sB);
        cudaStreamWaitEvent(sA, e, 0);
    };

    // L3 + L4: agg3(IN->MID) on sA; g3(MID->OUT) and g4(OUT->OUT4) interleaved on sB
    auto layer34 = [&](const __half* IN, __half* MID, __half* OUT, __half* OUT4,
                       const int* off_, const int2* ed_, const float* dv_) {
        for (int c = 0; c < NCH; c++) {
            int r0 = CST[c], rows = CROW[c];
            int n1 = r0 + rows; if (n1 > N) n1 = N;
            int nblk = ceil_div(n1 - r0, 8);
            agg_csr_h<256, false><<<nblk, 256, 0, sA>>>(IN, MID, off_, ed_, dv_,
                (const int*)0, (const float*)0, (float*)0, 0, r0, n1);
            cudaEvent_t e = g_ev[evc++];
            cudaEventRecord(e, sA);
            cudaStreamWaitEvent(sB, e, 0);
            hgemm<true, true><<<dim3(4, rows / 128), 256, 0, sB>>>(
                MID + (size_t)r0 * 256, w3h, bc3, OUT + (size_t)r0 * 256, rows, 256, 256, 256);
            hgemm<false, false><<<dim3(2, rows / 128), 256, 0, sB>>>(
                OUT + (size_t)r0 * 256, w4h, (const float*)0, OUT4 + (size_t)r0 * 128, rows, 256, 128, 128);
        }
        cudaEvent_t e = g_ev[evc++];
        cudaEventRecord(e, sB);
        cudaStreamWaitEvent(sA, e, 0);
    };

    // ---- prolog (sA): zero cbuf + cnts + pads, convert weights
    fill_kernel<<<ceil_div((long long)G * CCOLS, TB), TB>>>(cbuf, 0.0f, (size_t)G * CCOLS);
    fill_kernel<<<ceil_div(2 * G, TB), TB>>>(cnt, 0.0f, (size_t)(2 * G));
    fillh_kernel<<<ceil_div((long long)PADR * 128, TB), TB>>>(hA + (size_t)N * 256, (size_t)PADR * 128);
    fillh_kernel<<<ceil_div((long long)PADR * 128, TB), TB>>>(hB + (size_t)N * 256, (size_t)PADR * 128);
    fillh_kernel<<<ceil_div((long long)PADR * 128, TB), TB>>>(hC + (size_t)N * 256, (size_t)PADR * 128);
    fillh_kernel<<<ceil_div((long long)PADR * 64, TB), TB>>>(hD + (size_t)N * 128, (size_t)PADR * 64);
    fillh_kernel<<<ceil_div((long long)PADR * 64, TB), TB>>>(hA1 + (size_t)N * 128, (size_t)PADR * 64);
    fillh_kernel<<<ceil_div((long long)PADR * 64, TB), TB>>>(hX + (size_t)N * 128, (size_t)PADR * 64);
    f2h_kernel<<<ceil_div(128 * 256 / 2, TB), TB>>>(Wc1, w1h, 128 * 256 / 2);
    f2h_kernel<<<ceil_div(256 * 256 / 2, TB), TB>>>(Wc2, w2h, 256 * 256 / 2);
    f2h_kernel<<<ceil_div(256 * 256 / 2, TB), TB>>>(Wc3, w3h, 256 * 256 / 2);
    f2h_kernel<<<ceil_div(256 * 128 / 2, TB), TB>>>(Wc4, w4h, 256 * 128 / 2);

    cudaEvent_t evF = g_ev[evc++];
    cudaEventRecord(evF, sA);
    cudaStreamWaitEvent(sB, evF, 0);
    cudaStreamWaitEvent(sC, evF, 0);

    // ---- sC: tower-1 prep (CSR, f2h, L1 agg) + notes
    build_csr(sC, ei[1], deg + N, dinv + N, bsum + 128, off + N, cur + N, edges + (size_t)N_EDGES);
    f2h_kernel<<<ceil_div((long long)N * 64, TB), TB, 0, sC>>>(x[1], hX + (size_t)N_PAD * 128, (size_t)N * 64);
    agg_csr_h<128, false><<<AGG_FULL, 256, 0, sC>>>(hX + (size_t)N_PAD * 128, hA1,
        off + N, edges + (size_t)N_EDGES, dinv + N,
        (const int*)0, (const float*)0, (float*)0, 0, 0, N);
    cudaEvent_t evC1 = g_ev[evc++];
    cudaEventRecord(evC1, sC);
    tc_gemm<true, true><<<dim3(4, G / 128), 256, 0, sC>>>(notes[0], Wn1, bn1b, t1 + (size_t)G * HID, G, 128, 256, 256, 0);
    tc_gemm<true, true><<<dim3(2, G / 128), 256, 0, sC>>>(t1 + (size_t)G * HID, Wn2, bn2b, cbuf, G, 256, 128, CCOLS, 256);
    tc_gemm<true, true><<<dim3(4, G / 128), 256, 0, sC>>>(notes[1], Wn1, bn1b, t1 + (size_t)G * HID, G, 128, 256, 256, 0);
    tc_gemm<true, true><<<dim3(2, G / 128), 256, 0, sC>>>(t1 + (size_t)G * HID, Wn2, bn2b, cbuf, G, 256, 128, CCOLS, 256 + H2);
    cudaEvent_t evNotes = g_ev[evc++];
    cudaEventRecord(evNotes, sC);

    // ---- tower 0: CSR + f2h (sA), then pipelined layers
    build_csr(sA, ei[0], deg, dinv, bsum, off, cur, edges);
    f2h_kernel<<<ceil_div((long long)N * 64, TB), TB, 0, sA>>>(x[0], hX, (size_t)N * 64);

    layer(hX, hA, hB, w1h, bc1, true, 128, 256, off, edges, dinv);   // L1
    layer(hB, hC, hA, w2h, bc2, true, 256, 256, off, edges, dinv);   // L2
    layer34(hA, hC, hB, hD, off, edges, dinv);                       // L3 + L4 -> hD

    count_kernel<<<ceil_div(N, TB), TB, 0, sA>>>(batch[0], cnt, N);
    agg_csr_h<128, true><<<AGG_FULL, 256, 0, sA>>>(hD, (__half*)0, off, edges, dinv,
        batch[0], bc4, cbuf, 0, 0, N);
    pool_div_kernel<<<ceil_div(G * H2, TB), TB, 0, sA>>>(cbuf, cnt, 0);

    // ---- tower 1 L1 GEMM on sB (overlaps tower-0 pool on sA): hA1 -> hB
    cudaStreamWaitEvent(sB, evC1, 0);
    for (int c = 0; c < NCH; c++) {
        int r0 = CST[c], rows = CROW[c];
        hgemm<true, true><<<dim3(4, rows / 128), 256, 0, sB>>>(
            hA1 + (size_t)r0 * 128, w1h, bc1, hB + (size_t)r0 * 256, rows, 128, 256, 256);
    }
    {
        cudaEvent_t e = g_ev[evc++];
        cudaEventRecord(e, sB);
        cudaStreamWaitEvent(sA, e, 0);
    }

    // ---- tower 1: pipelined L2..L4 + pool
    const int* off1 = off + N;
    const int2* ed1 = edges + (size_t)N_EDGES;
    const float* dv1 = dinv + N;
    layer(hB, hC, hA, w2h, bc2, true, 256, 256, off1, ed1, dv1);     // L2
    layer34(hA, hC, hB, hD, off1, ed1, dv1);                         // L3 + L4 -> hD

    count_kernel<<<ceil_div(N, TB), TB, 0, sA>>>(batch[1], cnt + G, N);
    agg_csr_h<128, true><<<AGG_FULL, 256, 0, sA>>>(hD, (__half*)0, off1, ed1, dv1,
        batch[1], bc4, cbuf, H2, 0, N);
    pool_div_kernel<<<ceil_div(G * H2, TB), TB, 0, sA>>>(cbuf, cnt + G, H2);

    // ---- head (sA; wait notes)
    cudaStreamWaitEvent(sA, evNotes, 0);
    tc_gemm<true, true><<<dim3(4, G / 128), 256>>>(cbuf, Wf1, bf1, t1, G, 512, 256, 256, 0);
    bn_stats_kernel<<<256, 256>>>(t1, 256, mu, istd);
    bn_apply_kernel<<<ceil_div((long long)G * 256, TB), TB>>>(t1, mu, istd, g1, be1, 256, G * 256);

    tc_gemm<true, true><<<dim3(2, G / 128), 256>>>(t1, Wf2, bf2, t2, G, 256, 128, 128, 0);
    bn_stats_kernel<<<128, 256>>>(t2, 128, mu, istd);
    bn_apply_kernel<<<ceil_div((long long)G * 128, TB), TB>>>(t2, mu, istd, g2, be2, 128, G * 128);

    tc_gemm<false, true><<<dim3(2, G / 128), 256>>>(t2, Wf3, bf3, (float*)d_out, G, 128, 128, 128, 0);
}

// round 16
// speedup vs baseline: 1.0598x; 1.0598x over previous
#include <cuda_runtime.h>
#include <cuda_fp16.h>
#include <math.h>
#include <stdint.h>

#define N_NODES 200000
#define N_PAD   200064
#define N_EDGES 3200000
#define G_GRAPHS 8192
#define HID 256
#define H2 128
#define CCOLS 512
#define EPS 1e-5f
#define SCAN_CHUNK 2048

// ---------------- scratch (device globals; no runtime alloc) ----------------
__device__ __half g_hX[2 * (size_t)N_PAD * 128];
__device__ __half g_hA[(size_t)N_PAD * HID];
__device__ __half g_hB[(size_t)N_PAD * HID];
__device__ __half g_hA1[(size_t)N_PAD * 128];   // tower-1 L1 agg output (overlap)
__device__ __half g_w1h[128 * 256];
__device__ __half g_w2h[256 * 256];
__device__ __half g_w3h[256 * 256];
__device__ __half g_w4h[256 * 128];
__device__ float g_dinv[2 * N_NODES];
__device__ int   g_deg[2 * N_NODES];
__device__ int   g_off[2 * N_NODES];
__device__ int   g_cur[2 * N_NODES];
__device__ int   g_bsum[2 * 128];
__device__ int2  g_edge[2 * (size_t)N_EDGES];   // (src_row, half2(w,w) bits)
__device__ float g_cnt[2 * G_GRAPHS];
__device__ float g_c[(size_t)G_GRAPHS * CCOLS];
__device__ float g_t1[2 * (size_t)G_GRAPHS * HID];
__device__ float g_t2[(size_t)G_GRAPHS * H2];
__device__ float g_mu[HID];
__device__ float g_istd[HID];

__device__ __forceinline__ void red_add_v4(float* addr, float4 v) {
    asm volatile("red.global.add.v4.f32 [%0], {%1, %2, %3, %4};"
                 :: "l"(addr), "f"(v.x), "f"(v.y), "f"(v.z), "f"(v.w)
                 : "memory");
}

// ---------------- utility kernels ----------------
__global__ void fill_kernel(float* __restrict__ p, float v, size_t n) {
    size_t i = (size_t)blockIdx.x * blockDim.x + threadIdx.x;
    if (i < n) p[i] = v;
}

__global__ void fillh_kernel(__half* __restrict__ p, size_t n2) {
    size_t i = (size_t)blockIdx.x * blockDim.x + threadIdx.x;
    if (i < n2) ((__half2*)p)[i] = __floats2half2_rn(0.f, 0.f);
}

__global__ void f2h_kernel(const float* __restrict__ in, __half* __restrict__ out, size_t n2) {
    size_t i = (size_t)blockIdx.x * blockDim.x + threadIdx.x;
    if (i < n2) {
        float2 v = ((const float2*)in)[i];
        ((__half2*)out)[i] = __floats2half2_rn(v.x, v.y);
    }
}

__global__ void zero_int_kernel(int* __restrict__ p, int n) {
    int i = blockIdx.x * blockDim.x + threadIdx.x;
    if (i < n) p[i] = 0;
}

__global__ void hist_kernel(const int* __restrict__ cols, int* __restrict__ deg, int nE) {
    int i = blockIdx.x * blockDim.x + threadIdx.x;
    if (i < nE) atomicAdd(&deg[cols[i]], 1);
}

__global__ void dinv_kernel(const int* __restrict__ deg, float* __restrict__ dinv, int n) {
    int i = blockIdx.x * blockDim.x + threadIdx.x;
    if (i < n) dinv[i] = rsqrtf((float)deg[i] + 1.0f);
}

// ---------------- exclusive scan ----------------
__global__ void scan_partial_kernel(const int* __restrict__ deg, int* __restrict__ bsum, int n) {
    __shared__ int sh[256];
    int t = threadIdx.x;
    int base = blockIdx.x * SCAN_CHUNK + t * 8;
    int s = 0;
#pragma unroll
    for (int k = 0; k < 8; k++)
        if (base + k < n) s += deg[base + k];
    sh[t] = s;
    __syncthreads();
    for (int o = 128; o > 0; o >>= 1) {
        if (t < o) sh[t] += sh[t + o];
        __syncthreads();
    }
    if (t == 0) bsum[blockIdx.x] = sh[0];
}

__global__ void scan_top_kernel(int* __restrict__ bsum, int nb) {
    __shared__ int sh[256];
    int t = threadIdx.x;
    int v = (t < nb) ? bsum[t] : 0;
    sh[t] = v;
    __syncthreads();
    for (int o = 1; o < 256; o <<= 1) {
        int x = (t >= o) ? sh[t - o] : 0;
        __syncthreads();
        sh[t] += x;
        __syncthreads();
    }
    if (t < nb) bsum[t] = sh[t] - v;
}

__global__ void scan_apply_kernel(const int* __restrict__ deg, const int* __restrict__ bsum,
                                  int* __restrict__ off, int* __restrict__ cur, int n) {
    __shared__ int sh[256];
    int t = threadIdx.x;
    int base = blockIdx.x * SCAN_CHUNK + t * 8;
    int loc[8];
    int s = 0;
#pragma unroll
    for (int k = 0; k < 8; k++) {
        loc[k] = (base + k < n) ? deg[base + k] : 0;
        s += loc[k];
    }
    sh[t] = s;
    __syncthreads();
    for (int o = 1; o < 256; o <<= 1) {
        int x = (t >= o) ? sh[t - o] : 0;
        __syncthreads();
        sh[t] += x;
        __syncthreads();
    }
    int run = bsum[blockIdx.x] + sh[t] - s;
#pragma unroll
    for (int k = 0; k < 8; k++) {
        if (base + k < n) {
            off[base + k] = run;
            cur[base + k] = run;
            run += loc[k];
        }
    }
}

__global__ void csr_fill_kernel(const int* __restrict__ rows, const int* __restrict__ cols,
                                const float* __restrict__ dinv, int* __restrict__ cur,
                                int2* __restrict__ edges, int nE) {
    int e = blockIdx.x * blockDim.x + threadIdx.x;
    if (e >= nE) return;
    int c = cols[e], r = rows[e];
    int p = atomicAdd(&cur[c], 1);
    __half2 w2 = __float2half2_rn(dinv[r]);
    edges[p] = make_int2(r, *reinterpret_cast<int*>(&w2));
}

// ---------------- CSR gather aggregation, fp16 HFMA2 accumulation ----------------
template <int D, bool POOL>
__global__ __launch_bounds__(256) void agg_csr_h(
    const __half* __restrict__ in, __half* __restrict__ out,
    const int* __restrict__ off, const int2* __restrict__ edges,
    const float* __restrict__ dinv,
    const int* __restrict__ batch, const float* __restrict__ bias,
    float* __restrict__ cbuf, int coff, int n) {
    int node = blockIdx.x * (blockDim.x >> 5) + (threadIdx.x >> 5);
    if (node >= n) return;
    int lane = threadIdx.x & 31;
    int s = off[node];
    int e = (node == n - 1) ? N_EDGES : off[node + 1];
    float dc = dinv[node];

    constexpr int V2 = D / 64;
    __half2 acc0[V2], acc1[V2];
#pragma unroll
    for (int v = 0; v < V2; v++) {
        acc0[v] = __floats2half2_rn(0.f, 0.f);
        acc1[v] = __floats2half2_rn(0.f, 0.f);
    }

    if (D == 256) {
        int j = s;
        for (; j + 1 < e; j += 2) {
            int2 e0 = edges[j], e1 = edges[j + 1];
            __half2 w0 = *reinterpret_cast<__half2*>(&e0.y);
            __half2 w1 = *reinterpret_cast<__half2*>(&e1.y);
            uint4 x0 = *((const uint4*)(in + (size_t)e0.x * D) + lane);
            uint4 x1 = *((const uint4*)(in + (size_t)e1.x * D) + lane);
            const __half2* p0 = (const __half2*)&x0;
            const __half2* p1 = (const __half2*)&x1;
#pragma unroll
            for (int v = 0; v < 4; v++) {
                acc0[v] = __hfma2(p0[v], w0, acc0[v]);
                acc1[v] = __hfma2(p1[v], w1, acc1[v]);
            }
        }
        if (j < e) {
            int2 e0 = edges[j];
            __half2 w0 = *reinterpret_cast<__half2*>(&e0.y);
            uint4 x0 = *((const uint4*)(in + (size_t)e0.x * D) + lane);
            const __half2* p0 = (const __half2*)&x0;
#pragma unroll
            for (int v = 0; v < 4; v++) acc0[v] = __hfma2(p0[v], w0, acc0[v]);
        }
    } else {
        int j = s;
        for (; j + 1 < e; j += 2) {
            int2 e0 = edges[j], e1 = edges[j + 1];
            __half2 w0 = *reinterpret_cast<__half2*>(&e0.y);
            __half2 w1 = *reinterpret_cast<__half2*>(&e1.y);
            uint2 x0 = *((const uint2*)(in + (size_t)e0.x * D) + lane);
            uint2 x1 = *((const uint2*)(in + (size_t)e1.x * D) + lane);
            const __half2* p0 = (const __half2*)&x0;
            const __half2* p1 = (const __half2*)&x1;
#pragma unroll
            for (int v = 0; v < 2; v++) {
                acc0[v] = __hfma2(p0[v], w0, acc0[v]);
                acc1[v] = __hfma2(p1[v], w1, acc1[v]);
            }
        }
        if (j < e) {
            int2 e0 = edges[j];
            __half2 w0 = *reinterpret_cast<__half2*>(&e0.y);
            uint2 x0 = *((const uint2*)(in + (size_t)e0.x * D) + lane);
            const __half2* p0 = (const __half2*)&x0;
#pragma unroll
            for (int v = 0; v < 2; v++) acc0[v] = __hfma2(p0[v], w0, acc0[v]);
        }
    }

    float accf[2 * V2];
    if (D == 256) {
        uint4 u = *((const uint4*)(in + (size_t)node * D) + lane);
        const __half2* hp = (const __half2*)&u;
#pragma unroll
        for (int v = 0; v < 4; v++) {
            float2 f0 = __half22float2(acc0[v]);
            float2 f1 = __half22float2(acc1[v]);
            float2 fs = __half22float2(hp[v]);
            accf[2 * v]     = (f0.x + f1.x + dc * fs.x) * dc;
            accf[2 * v + 1] = (f0.y + f1.y + dc * fs.y) * dc;
        }
    } else {
        uint2 u = *((const uint2*)(in + (size_t)node * D) + lane);
        const __half2* hp = (const __half2*)&u;
#pragma unroll
        for (int v = 0; v < 2; v++) {
            float2 f0 = __half22float2(acc0[v]);
            float2 f1 = __half22float2(acc1[v]);
            float2 fs = __half22float2(hp[v]);
            accf[2 * v]     = (f0.x + f1.x + dc * fs.x) * dc;
            accf[2 * v + 1] = (f0.y + f1.y + dc * fs.y) * dc;
        }
    }

    if (POOL) {
        float4 b = *(const float4*)&bias[lane * 4];
        float4 v0;
        v0.x = fmaxf(accf[0] + b.x, 0.0f);
        v0.y = fmaxf(accf[1] + b.y, 0.0f);
        v0.z = fmaxf(accf[2] + b.z, 0.0f);
        v0.w = fmaxf(accf[3] + b.w, 0.0f);
        red_add_v4(&cbuf[(size_t)batch[node] * CCOLS + coff + lane * 4], v0);
    } else if (D == 256) {
        uint4 o;
        __half2* op = (__half2*)&o;
#pragma unroll
        for (int v = 0; v < 4; v++) op[v] = __floats2half2_rn(accf[2 * v], accf[2 * v + 1]);
        *((uint4*)(out + (size_t)node * D) + lane) = o;
    } else {
        uint2 o;
        __half2* op = (__half2*)&o;
#pragma unroll
        for (int v = 0; v < 2; v++) op[v] = __floats2half2_rn(accf[2 * v], accf[2 * v + 1]);
        *((uint2*)(out + (size_t)node * D) + lane) = o;
    }
}

__global__ void count_kernel(const int* __restrict__ batch, float* __restrict__ cnt, int n) {
    int i = blockIdx.x * blockDim.x + threadIdx.x;
    if (i < n) atomicAdd(&cnt[batch[i]], 1.0f);
}

__global__ void pool_div_kernel(float* __restrict__ c, const float* __restrict__ cnt, int coff) {
    int idx = blockIdx.x * blockDim.x + threadIdx.x;
    if (idx >= G_GRAPHS * H2) return;
    int g = idx >> 7, d = idx & 127;
    c[(size_t)g * CCOLS + coff + d] *= 1.0f / fmaxf(cnt[g], 1.0f);
}

// ---------------- fp16 HMMA GEMM, cp.async double-buffered ----------------
#define APAD 40
template <bool RELU, bool BIAS>
__global__ __launch_bounds__(256) void hgemm(
    const __half* __restrict__ A, const __half* __restrict__ W,
    const float* __restrict__ bias, __half* __restrict__ C,
    int M, int K, int N, int ldc) {
    __shared__ __half As[2][128][APAD];
    __shared__ __half Bst[2][64][APAD];

    int tid = threadIdx.x;
    int bm = blockIdx.y * 128, bn = blockIdx.x * 64;
    int warp = tid >> 5, lane = tid & 31;
    int wm = (warp & 3) * 32, wn = (warp >> 2) * 32;
    int g = lane >> 2, tig = lane & 3;

    int arow0 = (tid + 0) >> 2,   ac8_0 = ((tid + 0) & 3) << 3;
    int arow1 = (tid + 256) >> 2, ac8_1 = ((tid + 256) & 3) << 3;
    int bk = tid >> 3, bn0 = (tid & 7) << 3;

    float acc[2][4][4] = {};

    {
        uint32_t d0 = (uint32_t)__cvta_generic_to_shared(&As[0][arow0][ac8_0]);
        uint32_t d1 = (uint32_t)__cvta_generic_to_shared(&As[0][arow1][ac8_1]);
        const __half* s0 = A + (size_t)(bm + arow0) * K + ac8_0;
        const __half* s1 = A + (size_t)(bm + arow1) * K + ac8_1;
        asm volatile("cp.async.ca.shared.global [%0], [%1], 16;" :: "r"(d0), "l"(s0));
        asm volatile("cp.async.ca.shared.global [%0], [%1], 16;" :: "r"(d1), "l"(s1));
        asm volatile("cp.async.commit_group;");
        uint4 bv = *(const uint4*)(W + (size_t)bk * N + bn + bn0);
        const __half* hv = (const __half*)&bv;
        asm volatile("cp.async.wait_group 0;" ::: "memory");
#pragma unroll
        for (int i = 0; i < 8; i++) Bst[0][bn0 + i][bk] = hv[i];
        __syncthreads();
    }

    int nIter = K >> 5;
    for (int it = 0; it < nIter; it++) {
        int s = it & 1;
        if (it + 1 < nIter) {
            int k0 = (it + 1) << 5;
            uint32_t d0 = (uint32_t)__cvta_generic_to_shared(&As[s ^ 1][arow0][ac8_0]);
            uint32_t d1 = (uint32_t)__cvta_generic_to_shared(&As[s ^ 1][arow1][ac8_1]);
            const __half* s0 = A + (size_t)(bm + arow0) * K + k0 + ac8_0;
            const __half* s1 = A + (size_t)(bm + arow1) * K + k0 + ac8_1;
            asm volatile("cp.async.ca.shared.global [%0], [%1], 16;" :: "r"(d0), "l"(s0));
            asm volatile("cp.async.ca.shared.global [%0], [%1], 16;" :: "r"(d1), "l"(s1));
            asm volatile("cp.async.commit_group;");
            uint4 bv = *(const uint4*)(W + (size_t)(k0 + bk) * N + bn + bn0);
            const __half* hv = (const __half*)&bv;
#pragma unroll
            for (int i = 0; i < 8; i++) Bst[s ^ 1][bn0 + i][bk] = hv[i];
        }

#pragma unroll
        for (int k16 = 0; k16 < 32; k16 += 16) {
            uint32_t a[2][4], b[4][2];
#pragma unroll
            for (int mt = 0; mt < 2; mt++) {
                int m = wm + mt * 16 + g;
                a[mt][0] = *(const uint32_t*)&As[s][m][k16 + 2 * tig];
                a[mt][1] = *(const uint32_t*)&As[s][m + 8][k16 + 2 * tig];
                a[mt][2] = *(const uint32_t*)&As[s][m][k16 + 2 * tig + 8];
                a[mt][3] = *(const uint32_t*)&As[s][m + 8][k16 + 2 * tig + 8];
            }
#pragma unroll
            for (int nt = 0; nt < 4; nt++) {
                int n = wn + nt * 8 + g;
                b[nt][0] = *(const uint32_t*)&Bst[s][n][k16 + 2 * tig];
                b[nt][1] = *(const uint32_t*)&Bst[s][n][k16 + 2 * tig + 8];
            }
#pragma unroll
            for (int mt = 0; mt < 2; mt++)
#pragma unroll
                for (int nt = 0; nt < 4; nt++) {
                    asm volatile(
                        "mma.sync.aligned.m16n8k16.row.col.f32.f16.f16.f32 "
                        "{%0,%1,%2,%3}, {%4,%5,%6,%7}, {%8,%9}, {%0,%1,%2,%3};"
                        : "+f"(acc[mt][nt][0]), "+f"(acc[mt][nt][1]),
                          "+f"(acc[mt][nt][2]), "+f"(acc[mt][nt][3])
                        : "r"(a[mt][0]), "r"(a[mt][1]), "r"(a[mt][2]), "r"(a[mt][3]),
                          "r"(b[nt][0]), "r"(b[nt][1]));
                }
        }

        if (it + 1 < nIter)
            asm volatile("cp.async.wait_group 0;" ::: "memory");
        __syncthreads();
    }

#pragma unroll
    for (int mt = 0; mt < 2; mt++) {
        int row0 = bm + wm + mt * 16 + g;
#pragma unroll
        for (int nt = 0; nt < 4; nt++) {
            int col = bn + wn + nt * 8 + 2 * tig;
            float b0 = 0.f, b1 = 0.f;
            if (BIAS) { b0 = bias[col]; b1 = bias[col + 1]; }
            float v0 = acc[mt][nt][0] + b0;
            float v1 = acc[mt][nt][1] + b1;
            float v2 = acc[mt][nt][2] + b0;
            float v3 = acc[mt][nt][3] + b1;
            if (RELU) {
                v0 = fmaxf(v0, 0.f); v1 = fmaxf(v1, 0.f);
                v2 = fmaxf(v2, 0.f); v3 = fmaxf(v3, 0.f);
            }
            *(__half2*)&C[(size_t)row0 * ldc + col] = __floats2half2_rn(v0, v1);
            *(__half2*)&C[(size_t)(row0 + 8) * ldc + col] = __floats2half2_rn(v2, v3);
        }
    }
}

// ---------------- tf32 GEMM (notes/head) ----------------
__device__ __forceinline__ void tf32_split(float x, uint32_t& h, uint32_t& l) {
    asm("cvt.rna.tf32.f32 %0, %1;" : "=r"(h) : "f"(x));
    float r = x - __uint_as_float(h);
    asm("cvt.rna.tf32.f32 %0, %1;" : "=r"(l) : "f"(r));
}

__device__ __forceinline__ void mma_tf32(float* c,
                                         uint32_t a0, uint32_t a1, uint32_t a2, uint32_t a3,
                                         uint32_t b0, uint32_t b1) {
    asm volatile(
        "mma.sync.aligned.m16n8k8.row.col.f32.tf32.tf32.f32 "
        "{%0,%1,%2,%3}, {%4,%5,%6,%7}, {%8,%9}, {%0,%1,%2,%3};"
        : "+f"(c[0]), "+f"(c[1]), "+f"(c[2]), "+f"(c[3])
        : "r"(a0), "r"(a1), "r"(a2), "r"(a3), "r"(b0), "r"(b1));
}

template <bool RELU, bool BIAS>
__global__ __launch_bounds__(256) void tc_gemm(
    const float* __restrict__ A, const float* __restrict__ W,
    const float* __restrict__ bias, float* __restrict__ C,
    int M, int K, int N, int ldc, int coff) {
    __shared__ float As[128][20];
    __shared__ float Bs[16][72];

    int tid = threadIdx.x;
    int bm = blockIdx.y * 128, bn = blockIdx.x * 64;
    int warp = tid >> 5, lane = tid & 31;
    int wm = (warp & 3) * 32, wn = (warp >> 2) * 32;
    int g = lane >> 2, tig = lane & 3;

    float acc[2][4][4] = {};

    for (int k0 = 0; k0 < K; k0 += 16) {
#pragma unroll
        for (int i = 0; i < 2; i++) {
            int idx = tid + i * 256;
            int row = idx >> 2, c4 = (idx & 3) << 2;
            float4 v = *(const float4*)&A[(size_t)(bm + row) * K + k0 + c4];
            As[row][c4 + 0] = v.x; As[row][c4 + 1] = v.y;
            As[row][c4 + 2] = v.z; As[row][c4 + 3] = v.w;
        }
        {
            int row = tid >> 4, c4 = (tid & 15) << 2;
            float4 v = *(const float4*)&W[(size_t)(k0 + row) * N + bn + c4];
            Bs[row][c4 + 0] = v.x; Bs[row][c4 + 1] = v.y;
            Bs[row][c4 + 2] = v.z; Bs[row][c4 + 3] = v.w;
        }
        __syncthreads();

#pragma unroll
        for (int k8 = 0; k8 < 16; k8 += 8) {
            uint32_t ah[2][4], al[2][4], bh[4][2], bl[4][2];
#pragma unroll
            for (int mt = 0; mt < 2; mt++) {
                int m = wm + mt * 16 + g;
                tf32_split(As[m][k8 + tig],         ah[mt][0], al[mt][0]);
                tf32_split(As[m + 8][k8 + tig],     ah[mt][1], al[mt][1]);
                tf32_split(As[m][k8 + tig + 4],     ah[mt][2], al[mt][2]);
                tf32_split(As[m + 8][k8 + tig + 4], ah[mt][3], al[mt][3]);
            }
#pragma unroll
            for (int nt = 0; nt < 4; nt++) {
                int n = wn + nt * 8 + g;
                tf32_split(Bs[k8 + tig][n],     bh[nt][0], bl[nt][0]);
                tf32_split(Bs[k8 + tig + 4][n], bh[nt][1], bl[nt][1]);
            }
#pragma unroll
            for (int mt = 0; mt < 2; mt++)
#pragma unroll
                for (int nt = 0; nt < 4; nt++) {
                    mma_tf32(acc[mt][nt], ah[mt][0], ah[mt][1], ah[mt][2], ah[mt][3],
                             bh[nt][0], bh[nt][1]);
                    mma_tf32(acc[mt][nt], ah[mt][0], ah[mt][1], ah[mt][2], ah[mt][3],
                             bl[nt][0], bl[nt][1]);
                    mma_tf32(acc[mt][nt], al[mt][0], al[mt][1], al[mt][2], al[mt][3],
                             bh[nt][0], bh[nt][1]);
                }
        }
        __syncthreads();
    }

#pragma unroll
    for (int mt = 0; mt < 2; mt++) {
        int row0 = bm + wm + mt * 16 + g;
#pragma unroll
        for (int nt = 0; nt < 4; nt++) {
            int col = bn + wn + nt * 8 + 2 * tig;
            float b0 = 0.f, b1 = 0.f;
            if (BIAS) { b0 = bias[col]; b1 = bias[col + 1]; }
            float v0 = acc[mt][nt][0] + b0;
            float v1 = acc[mt][nt][1] + b1;
            float v2 = acc[mt][nt][2] + b0;
            float v3 = acc[mt][nt][3] + b1;
            if (RELU) {
                v0 = fmaxf(v0, 0.f); v1 = fmaxf(v1, 0.f);
                v2 = fmaxf(v2, 0.f); v3 = fmaxf(v3, 0.f);
            }
            *(float2*)&C[(size_t)row0 * ldc + coff + col] = make_float2(v0, v1);
            *(float2*)&C[(size_t)(row0 + 8) * ldc + coff + col] = make_float2(v2, v3);
        }
    }
}

// ---------------- batch norm ----------------
__global__ void bn_stats_kernel(const float* __restrict__ X, int C,
                                float* __restrict__ mu, float* __restrict__ istd) {
    int c = blockIdx.x;
    int tid = threadIdx.x;
    float s = 0.f, s2 = 0.f;
    for (int r = tid; r < G_GRAPHS; r += 256) {
        float v = X[(size_t)r * C + c];
        s += v;
        s2 += v * v;
    }
    __shared__ float sh[256], sh2[256];
    sh[tid] = s;
    sh2[tid] = s2;
    __syncthreads();
    for (int o = 128; o > 0; o >>= 1) {
        if (tid < o) {
            sh[tid] += sh[tid + o];
            sh2[tid] += sh2[tid + o];
        }
        __syncthreads();
    }
    if (tid == 0) {
        float m = sh[0] / (float)G_GRAPHS;
        float var = sh2[0] / (float)G_GRAPHS - m * m;
        mu[c] = m;
        istd[c] = rsqrtf(var + EPS);
    }
}

__global__ void bn_apply_kernel(float* __restrict__ X, const float* __restrict__ mu,
                                const float* __restrict__ istd, const float* __restrict__ gamma,
                                const float* __restrict__ beta, int C, int total) {
    int idx = blockIdx.x * blockDim.x + threadIdx.x;
    if (idx >= total) return;
    int c = idx % C;
    X[idx] = (X[idx] - mu[c]) * istd[c] * gamma[c] + beta[c];
}

// ---------------- host launcher ----------------
static inline int ceil_div(long long a, int b) { return (int)((a + b - 1) / b); }

static void build_csr(cudaStream_t st, const int* ei,
                      int* deg, float* dinv, int* bsum, int* off, int* cur, int2* edges) {
    const int TB = 256;
    const int N = N_NODES, E = N_EDGES;
    const int NB_SCAN = ceil_div(N, SCAN_CHUNK);
    const int* rows = ei;
    const int* cols = ei + E;
    zero_int_kernel<<<ceil_div(N, TB), TB, 0, st>>>(deg, N);
    hist_kernel<<<ceil_div(E, TB), TB, 0, st>>>(cols, deg, E);
    dinv_kernel<<<ceil_div(N, TB), TB, 0, st>>>(deg, dinv, N);
    scan_partial_kernel<<<NB_SCAN, 256, 0, st>>>(deg, bsum, N);
    scan_top_kernel<<<1, 256, 0, st>>>(bsum, NB_SCAN);
    scan_apply_kernel<<<NB_SCAN, 256, 0, st>>>(deg, bsum, off, cur, N);
    csr_fill_kernel<<<ceil_div(E, TB), TB, 0, st>>>(rows, cols, dinv, cur, edges, E);
}

// GCN layers 1..4 + pool; if preAgg != 0, layer-1 aggregation was already done.
static void run_tower_layers(cudaStream_t st, int t, const __half* preAgg,
                             const int* batch, const float* bc1, const float* bc2,
                             const float* bc3, const float* bc4,
                             __half* hX, __half* hA, __half* hB,
                             __half* w1h, __half* w2h, __half* w3h, __half* w4h,
                             float* dinv, int* off, int2* edges,
                             float* cnt, float* cbuf) {
    const int TB = 256;
    const int N = N_NODES, G = G_GRAPHS;
    const int MPAD = N_PAD;
    const int AGG_BLK = ceil_div(N, 8);

    const __half* gemm1_in;
    if (preAgg) {
        gemm1_in = preAgg;
    } else {
        agg_csr_h<128, false><<<AGG_BLK, 256, 0, st>>>(hX, hA, off, edges, dinv,
                                                       (const int*)0, (const float*)0, (float*)0, 0, N);
        gemm1_in = hA;
    }
    hgemm<true, true><<<dim3(4, MPAD / 128), 256, 0, st>>>(gemm1_in, w1h, bc1, hB, MPAD, 128, 256, 256);

    agg_csr_h<256, false><<<AGG_BLK, 256, 0, st>>>(hB, hA, off, edges, dinv,
                                                   (const int*)0, (const float*)0, (float*)0, 0, N);
    hgemm<true, true><<<dim3(4, MPAD / 128), 256, 0, st>>>(hA, w2h, bc2, hB, MPAD, 256, 256, 256);

    agg_csr_h<256, false><<<AGG_BLK, 256, 0, st>>>(hB, hA, off, edges, dinv,
                                                   (const int*)0, (const float*)0, (float*)0, 0, N);
    hgemm<true, true><<<dim3(4, MPAD / 128), 256, 0, st>>>(hA, w3h, bc3, hB, MPAD, 256, 256, 256);

    hgemm<false, false><<<dim3(2, MPAD / 128), 256, 0, st>>>(hB, w4h, (const float*)0, hA, MPAD, 256, 128, 128);
    count_kernel<<<ceil_div(N, TB), TB, 0, st>>>(batch, cnt, N);
    agg_csr_h<128, true><<<AGG_BLK, 256, 0, st>>>(hA, (__half*)0, off, edges, dinv,
                                                  batch, bc4, cbuf, t * H2, N);
    pool_div_kernel<<<ceil_div(G * H2, TB), TB, 0, st>>>(cbuf, cnt, t * H2);
}

extern "C" void kernel_launch(void* const* d_in, const int* in_sizes, int n_in,
                              void* d_out, int out_size) {
    const float* x[2] = {(const float*)d_in[0], (const float*)d_in[1]};
    const int* ei[2] = {(const int*)d_in[2], (const int*)d_in[3]};
    const int* batch[2] = {(const int*)d_in[4], (const int*)d_in[5]};
    const float* notes[2] = {(const float*)d_in[6], (const float*)d_in[7]};
    const float* Wc1 = (const float*)d_in[8];  const float* bc1 = (const float*)d_in[9];
    const float* Wc2 = (const float*)d_in[10]; const float* bc2 = (const float*)d_in[11];
    const float* Wc3 = (const float*)d_in[12]; const float* bc3 = (const float*)d_in[13];
    const float* Wc4 = (const float*)d_in[14]; const float* bc4 = (const float*)d_in[15];
    const float* Wn1 = (const float*)d_in[16]; const float* bn1b = (const float*)d_in[17];
    const float* Wn2 = (const float*)d_in[18]; const float* bn2b = (const float*)d_in[19];
    const float* Wf1 = (const float*)d_in[20]; const float* bf1 = (const float*)d_in[21];
    const float* g1 = (const float*)d_in[22];  const float* be1 = (const float*)d_in[23];
    const float* Wf2 = (const float*)d_in[24]; const float* bf2 = (const float*)d_in[25];
    const float* g2 = (const float*)d_in[26];  const float* be2 = (const float*)d_in[27];
    const float* Wf3 = (const float*)d_in[28]; const float* bf3 = (const float*)d_in[29];

    __half *hX, *hA, *hB, *hA1, *w1h, *w2h, *w3h, *w4h;
    float *dinv, *cnt, *cbuf, *t1, *t2, *mu, *istd;
    int *deg, *off, *cur, *bsum;
    int2* edges;
    cudaGetSymbolAddress((void**)&hX, g_hX);
    cudaGetSymbolAddress((void**)&hA, g_hA);
    cudaGetSymbolAddress((void**)&hB, g_hB);
    cudaGetSymbolAddress((void**)&hA1, g_hA1);
    cudaGetSymbolAddress((void**)&w1h, g_w1h);
    cudaGetSymbolAddress((void**)&w2h, g_w2h);
    cudaGetSymbolAddress((void**)&w3h, g_w3h);
    cudaGetSymbolAddress((void**)&w4h, g_w4h);
    cudaGetSymbolAddress((void**)&dinv, g_dinv);
    cudaGetSymbolAddress((void**)&deg, g_deg);
    cudaGetSymbolAddress((void**)&off, g_off);
    cudaGetSymbolAddress((void**)&cur, g_cur);
    cudaGetSymbolAddress((void**)&bsum, g_bsum);
    cudaGetSymbolAddress((void**)&edges, g_edge);
    cudaGetSymbolAddress((void**)&cnt, g_cnt);
    cudaGetSymbolAddress((void**)&cbuf, g_c);
    cudaGetSymbolAddress((void**)&t1, g_t1);
    cudaGetSymbolAddress((void**)&t2, g_t2);
    cudaGetSymbolAddress((void**)&mu, g_mu);
    cudaGetSymbolAddress((void**)&istd, g_istd);

    static cudaStream_t sB = 0, sC = 0;
    static cudaEvent_t evRoot = 0, evFill = 0, evProl = 0, evC1 = 0, evNotes = 0;
    if (sB == 0) {
        cudaStreamCreateWithFlags(&sB, cudaStreamNonBlocking);
        cudaStreamCreateWithFlags(&sC, cudaStreamNonBlocking);
        cudaEventCreateWithFlags(&evRoot, cudaEventDisableTiming);
        cudaEventCreateWithFlags(&evFill, cudaEventDisableTiming);
        cudaEventCreateWithFlags(&evProl, cudaEventDisableTiming);
        cudaEventCreateWithFlags(&evC1, cudaEventDisableTiming);
        cudaEventCreateWithFlags(&evNotes, cudaEventDisableTiming);
    }

    const int TB = 256;
    const int G = G_GRAPHS;
    const int N = N_NODES;
    const int PADR = N_PAD - N_NODES;
    const int AGG_BLK = ceil_div(N, 8);

    // ---- fork from the capturing stream FIRST (graph-capture requirement)
    cudaEventRecord(evRoot, 0);
    cudaStreamWaitEvent(sB, evRoot, 0);
    cudaStreamWaitEvent(sC, evRoot, 0);

    // ---- prolog on sB (off the critical path): cbuf/cnt zero, pads, weights, f2h(x0)
    fill_kernel<<<ceil_div((long long)G * CCOLS, TB), TB, 0, sB>>>(cbuf, 0.0f, (size_t)G * CCOLS);
    fill_kernel<<<ceil_div(2 * G, TB), TB, 0, sB>>>(cnt, 0.0f, (size_t)(2 * G));
    cudaEventRecord(evFill, sB);
    fillh_kernel<<<ceil_div((long long)PADR * 64, TB), TB, 0, sB>>>(hA + (size_t)N * 128, (size_t)PADR * 64);
    fillh_kernel<<<ceil_div((long long)PADR * 128, TB), TB, 0, sB>>>(hA + (size_t)N * 256, (size_t)PADR * 128);
    fillh_kernel<<<ceil_div((long long)PADR * 64, TB), TB, 0, sB>>>(hB + (size_t)N * 128, (size_t)PADR * 64);
    fillh_kernel<<<ceil_div((long long)PADR * 128, TB), TB, 0, sB>>>(hB + (size_t)N * 256, (size_t)PADR * 128);
    fillh_kernel<<<ceil_div((long long)PADR * 64, TB), TB, 0, sB>>>(hA1 + (size_t)N * 128, (size_t)PADR * 64);
    f2h_kernel<<<ceil_div(128 * 256 / 2, TB), TB, 0, sB>>>(Wc1, w1h, 128 * 256 / 2);
    f2h_kernel<<<ceil_div(256 * 256 / 2, TB), TB, 0, sB>>>(Wc2, w2h, 256 * 256 / 2);
    f2h_kernel<<<ceil_div(256 * 256 / 2, TB), TB, 0, sB>>>(Wc3, w3h, 256 * 256 / 2);
    f2h_kernel<<<ceil_div(256 * 128 / 2, TB), TB, 0, sB>>>(Wc4, w4h, 256 * 128 / 2);
    f2h_kernel<<<ceil_div((long long)N * 64, TB), TB, 0, sB>>>(x[0], hX, (size_t)N * 64);
    cudaEventRecord(evProl, sB);

    // ---- sC: tower-1 prep (CSR, f2h, L1 agg) + notes
    build_csr(sC, ei[1], deg + N, dinv + N, bsum + 128, off + N, cur + N,
              edges + (size_t)N_EDGES);
    f2h_kernel<<<ceil_div((long long)N * 64, TB), TB, 0, sC>>>(x[1], hX + (size_t)N_PAD * 128, (size_t)N * 64);
    agg_csr_h<128, false><<<AGG_BLK, 256, 0, sC>>>(hX + (size_t)N_PAD * 128, hA1,
                                                   off + N, edges + (size_t)N_EDGES, dinv + N,
                                                   (const int*)0, (const float*)0, (float*)0, 0, N);
    cudaEventRecord(evC1, sC);
    cudaStreamWaitEvent(sC, evFill, 0);   // cbuf zeroed before notes write into it
    tc_gemm<true, true><<<dim3(4, G / 128), 256, 0, sC>>>(notes[0], Wn1, bn1b, t1 + (size_t)G * HID, G, 128, 256, 256, 0);
    tc_gemm<true, true><<<dim3(2, G / 128), 256, 0, sC>>>(t1 + (size_t)G * HID, Wn2, bn2b, cbuf, G, 256, 128, CCOLS, 256);
    tc_gemm<true, true><<<dim3(4, G / 128), 256, 0, sC>>>(notes[1], Wn1, bn1b, t1 + (size_t)G * HID, G, 128, 256, 256, 0);
    tc_gemm<true, true><<<dim3(2, G / 128), 256, 0, sC>>>(t1 + (size_t)G * HID, Wn2, bn2b, cbuf, G, 256, 128, CCOLS, 256 + H2);
    cudaEventRecord(evNotes, sC);

    // ---- stream 0: tower 0 CSR starts immediately (overlaps sB prolog + sC prep)
    build_csr((cudaStream_t)0, ei[0], deg, dinv, bsum, off, cur, edges);
    cudaStreamWaitEvent((cudaStream_t)0, evProl, 0);   // hX0/pads/weights/cbuf ready
    run_tower_layers((cudaStream_t)0, 0, (const __half*)0, batch[0], bc1, bc2, bc3, bc4,
                     hX, hA, hB, w1h, w2h, w3h, w4h, dinv, off, edges, cnt, cbuf);

    // ---- tower 1 (layer-1 agg already in hA1 from sC)
    cudaStreamWaitEvent((cudaStream_t)0, evC1, 0);
    run_tower_layers((cudaStream_t)0, 1, hA1, batch[1], bc1, bc2, bc3, bc4,
                     hX + (size_t)N_PAD * 128, hA, hB, w1h, w2h, w3h, w4h,
                     dinv + N, off + N, edges + (size_t)N_EDGES, cnt + G, cbuf);

    // ---- join notes before head
    cudaStreamWaitEvent((cudaStream_t)0, evNotes, 0);

    // ---- head
    tc_gemm<true, true><<<dim3(4, G / 128), 256>>>(cbuf, Wf1, bf1, t1, G, 512, 256, 256, 0);
    bn_stats_kernel<<<256, 256>>>(t1, 256, mu, istd);
    bn_apply_kernel<<<ceil_div((long long)G * 256, TB), TB>>>(t1, mu, istd, g1, be1, 256, G * 256);

    tc_gemm<true, true><<<dim3(2, G / 128), 256>>>(t1, Wf2, bf2, t2, G, 256, 128, 128, 0);
    bn_stats_kernel<<<128, 256>>>(t2, 128, mu, istd);
    bn_apply_kernel<<<ceil_div((long long)G * 128, TB), TB>>>(t2, mu, istd, g2, be2, 128, G * 128);

    tc_gemm<false, true><<<dim3(2, G / 128), 256>>>(t2, Wf3, bf3, (float*)d_out, G, 128, 128, 128, 0);
}